// round 7
// baseline (speedup 1.0000x reference)
#include <cuda_runtime.h>
#include <math_constants.h>
#include <stdint.h>

// WindowRouting: out[b,q,0:4] = indices of top-4 over m of dot(Q[b,q,:], I[b,m,:]).
// Positive scale cannot change ordering -> skipped.
// Shapes fixed by the reference: B=4, Nq=4096, M=8192, K=128.
//
// SINGLE CHANGE vs R6: output written as float32 (value = (float)index).
// Hypothesis: harness __output__ dtype is float32; int writes read as denormals
// (~0) made rel_err exactly 1.000000 in every prior round.

#define KDIM 128
#define NB   4
#define NQ   4096
#define MM   8192

__global__ __launch_bounds__(256, 1)
void window_routing_simple(const float* __restrict__ query,
                           const float* __restrict__ image,
                           float* __restrict__ out)
{
    const int lane = threadIdx.x & 31;
    const int warp = threadIdx.x >> 5;
    const int b    = blockIdx.y;
    const int q    = blockIdx.x * 8 + warp;     // 8 warps per block

    // lane c holds q[c], q[c+32], q[c+64], q[c+96]  (coalesced loads)
    const float* qrow = query + ((size_t)b * NQ + q) * KDIM;
    const float q0 = qrow[lane];
    const float q1 = qrow[lane + 32];
    const float q2 = qrow[lane + 64];
    const float q3 = qrow[lane + 96];

    const float* ibase = image + (size_t)b * MM * KDIM;

    float tv0 = -CUDART_INF_F, tv1 = -CUDART_INF_F,
          tv2 = -CUDART_INF_F, tv3 = -CUDART_INF_F;
    int   ti0 = 0, ti1 = 0, ti2 = 0, ti3 = 0;

    #pragma unroll 4
    for (int m = 0; m < MM; ++m) {
        const float* irow = ibase + (size_t)m * KDIM;
        float p = q0 * irow[lane]
                + q1 * irow[lane + 32]
                + q2 * irow[lane + 64]
                + q3 * irow[lane + 96];
        // full warp sum; afterwards every lane holds the same dot product
        p += __shfl_xor_sync(0xffffffffu, p, 16);
        p += __shfl_xor_sync(0xffffffffu, p, 8);
        p += __shfl_xor_sync(0xffffffffu, p, 4);
        p += __shfl_xor_sync(0xffffffffu, p, 2);
        p += __shfl_xor_sync(0xffffffffu, p, 1);

        // m strictly increasing -> strict '>' keeps lowest index on ties
        if (p > tv3) {
            if (p > tv0) {
                tv3 = tv2; ti3 = ti2; tv2 = tv1; ti2 = ti1;
                tv1 = tv0; ti1 = ti0; tv0 = p;  ti0 = m;
            } else if (p > tv1) {
                tv3 = tv2; ti3 = ti2; tv2 = tv1; ti2 = ti1;
                tv1 = p;  ti1 = m;
            } else if (p > tv2) {
                tv3 = tv2; ti3 = ti2; tv2 = p; ti2 = m;
            } else {
                tv3 = p;  ti3 = m;
            }
        }
    }

    if (lane == 0) {
        float* o = out + ((size_t)b * NQ + q) * 4;
        o[0] = (float)ti0; o[1] = (float)ti1;
        o[2] = (float)ti2; o[3] = (float)ti3;
    }
}

extern "C" void kernel_launch(void* const* d_in, const int* in_sizes, int n_in,
                              void* d_out, int out_size)
{
    // Metadata order, no heuristics: d_in[0]=query, d_in[1]=image.
    (void)in_sizes; (void)n_in; (void)out_size;
    const float* query = (const float*)d_in[0];
    const float* image = (const float*)d_in[1];
    float* out = (float*)d_out;

    dim3 grid(NQ / 8, NB);   // (512, 4), 8 q-rows per 256-thread block
    window_routing_simple<<<grid, 256>>>(query, image, out);
}

// round 8
// speedup vs baseline: 4.0897x; 4.0897x over previous
#include <cuda_runtime.h>
#include <math_constants.h>
#include <stdint.h>

// WindowRouting: out[b,q,0:4] = (float)indices of top-4 over m of
// dot(Q[b,q,:], I[b,m,:]).  Positive scale cannot change ordering -> skipped.
// Shapes fixed: B=4, Nq=4096, M=8192, K=128.  OUTPUT DTYPE IS FLOAT32.
//
// Fused fp32 register-tiled GEMM + running top-4.
// Block: TQ=64 q-rows x TM=128 m-rows, K=128 whole depth in smem.
// 256 threads as 16(tx:m) x 16(ty:q); per-thread 4q x 8m tile.
// 16B-chunk XOR swizzle (chunk c of row r at c ^ (r&7)) -> conflict-free LDS.128.

#define KDIM 128
#define NB   4
#define NQ   4096
#define MM   8192
#define TQ   64
#define TM   128
#define NTH  256

__global__ __launch_bounds__(NTH, 1)
void window_routing_tiled(const float* __restrict__ query,
                          const float* __restrict__ image,
                          float* __restrict__ out)
{
    extern __shared__ float4 smem4[];
    float4* Qs = smem4;              // TQ*32 float4 = 32 KB
    float4* Is = smem4 + TQ * 32;    // TM*32 float4 = 64 KB  (96 KB total)

    const int t  = threadIdx.x;
    const int tx = t & 15;           // m-direction
    const int ty = t >> 4;           // q-direction
    const int b  = blockIdx.y;
    const int q0 = blockIdx.x * TQ;

    const float* ibase = image + (size_t)b * MM * KDIM;

    // ---- load Q tile once ----
    #pragma unroll
    for (int it = 0; it < (TQ * 32) / NTH; ++it) {
        int lin = it * NTH + t;
        int r = lin >> 5;
        int c = lin & 31;
        const float* src = query + ((size_t)b * NQ + (q0 + r)) * KDIM;
        Qs[r * 32 + (c ^ (r & 7))] = ((const float4*)src)[c];
    }

    // running top-4 per owned q-row (q = ty + 16*i, i<4)
    float topv[4][4];
    int   topi[4][4];
    #pragma unroll
    for (int i = 0; i < 4; ++i)
        #pragma unroll
        for (int s = 0; s < 4; ++s) { topv[i][s] = -CUDART_INF_F; topi[i][s] = 0x7FFFFFFF; }

    const int qsw = ty & 7;
    const int isw = tx & 7;

    for (int mt = 0; mt < MM; mt += TM) {
        __syncthreads();  // previous tile's reads done; also covers Q visibility
        #pragma unroll
        for (int it = 0; it < (TM * 32) / NTH; ++it) {
            int lin = it * NTH + t;
            int r = lin >> 5;
            int c = lin & 31;
            Is[r * 32 + (c ^ (r & 7))] = ((const float4*)(ibase + (size_t)(mt + r) * KDIM))[c];
        }
        __syncthreads();

        float acc[4][8];
        #pragma unroll
        for (int i = 0; i < 4; ++i)
            #pragma unroll
            for (int j = 0; j < 8; ++j) acc[i][j] = 0.0f;

        #pragma unroll 4
        for (int k4 = 0; k4 < 32; ++k4) {
            float4 qf[4], iff[8];
            #pragma unroll
            for (int i = 0; i < 4; ++i)
                qf[i] = Qs[(ty + 16 * i) * 32 + (k4 ^ qsw)];
            #pragma unroll
            for (int j = 0; j < 8; ++j)
                iff[j] = Is[(tx + 16 * j) * 32 + (k4 ^ isw)];
            #pragma unroll
            for (int i = 0; i < 4; ++i)
                #pragma unroll
                for (int j = 0; j < 8; ++j) {
                    acc[i][j] += qf[i].x * iff[j].x;
                    acc[i][j] += qf[i].y * iff[j].y;
                    acc[i][j] += qf[i].z * iff[j].z;
                    acc[i][j] += qf[i].w * iff[j].w;
                }
        }

        // fold: within a tile, j ascending => m ascending for this thread;
        // across tiles mt ascending. strict '>' keeps lowest index on ties.
        #pragma unroll
        for (int j = 0; j < 8; ++j) {
            int mg = mt + tx + 16 * j;
            #pragma unroll
            for (int i = 0; i < 4; ++i) {
                float v = acc[i][j];
                if (v > topv[i][3]) {
                    topv[i][3] = v; topi[i][3] = mg;
                    #pragma unroll
                    for (int s = 3; s >= 1; --s) {
                        bool sw = (topv[i][s] > topv[i][s-1]) ||
                                  (topv[i][s] == topv[i][s-1] && topi[i][s] < topi[i][s-1]);
                        if (sw) {
                            float tv = topv[i][s]; topv[i][s] = topv[i][s-1]; topv[i][s-1] = tv;
                            int   ti = topi[i][s]; topi[i][s] = topi[i][s-1]; topi[i][s-1] = ti;
                        }
                    }
                }
            }
        }
    }

    // ---- cross-thread merge: 16 tx-threads x 4 candidates per q-row ----
    __syncthreads();
    float* cval = (float*)Qs;                 // TQ*16*4 floats = 16 KB
    int*   cidx = (int*)Qs + TQ * 16 * 4;     // next 16 KB (within Qs's 32 KB)

    #pragma unroll
    for (int i = 0; i < 4; ++i) {
        int q = ty + 16 * i;
        #pragma unroll
        for (int s = 0; s < 4; ++s) {
            cval[(q * 16 + tx) * 4 + s] = topv[i][s];
            cidx[(q * 16 + tx) * 4 + s] = topi[i][s];
        }
    }
    __syncthreads();

    if (t < TQ) {
        int q = t;
        int base = q * 64;
        int res[4];
        #pragma unroll
        for (int pick = 0; pick < 4; ++pick) {
            float best = -CUDART_INF_F;
            int bi = 0x7FFFFFFF, bc = 0;
            for (int c = 0; c < 64; ++c) {
                float v = cval[base + c];
                int   id = cidx[base + c];
                if (v > best || (v == best && id < bi)) { best = v; bi = id; bc = c; }
            }
            res[pick] = bi;
            cval[base + bc] = -CUDART_INF_F;   // remove picked candidate
        }
        float* o = out + ((size_t)b * NQ + (q0 + q)) * 4;
        #pragma unroll
        for (int s = 0; s < 4; ++s) o[s] = (float)res[s];
    }
}

extern "C" void kernel_launch(void* const* d_in, const int* in_sizes, int n_in,
                              void* d_out, int out_size)
{
    (void)in_sizes; (void)n_in; (void)out_size;
    const float* query = (const float*)d_in[0];
    const float* image = (const float*)d_in[1];
    float* out = (float*)d_out;

    const int smem_bytes = (TQ * 32 + TM * 32) * (int)sizeof(float4);  // 96 KB
    cudaFuncSetAttribute(window_routing_tiled,
                         cudaFuncAttributeMaxDynamicSharedMemorySize, smem_bytes);

    dim3 grid(NQ / TQ, NB);   // (64, 4) = 256 blocks
    window_routing_tiled<<<grid, NTH, smem_bytes>>>(query, image, out);
}